// round 1
// baseline (speedup 1.0000x reference)
#include <cuda_runtime.h>
#include <stdint.h>

#define BATCH   32768
#define NTREE   256
#define NNODE   2047
#define NPAD    2048
#define NFEAT   256
#define NCLS    8
#define DEPTH   10
#define SCHUNK  128      // samples per block
#define THREADS 512      // 4 "tree lanes" x 128 samples

// Scratch (device globals: allowed, no allocation)
__device__ uint2 g_nodes[NTREE * NPAD];   // {threshold bits, feature * SCHUNK*4 (byte offset)}
__device__ float g_xT[NFEAT * BATCH];     // x transposed [feature][sample]

// ---------------- prep: pack nodes ----------------
__global__ void prep_nodes_k(const int* __restrict__ features,
                             const float* __restrict__ thresholds) {
    int i = blockIdx.x * blockDim.x + threadIdx.x;
    if (i >= NTREE * NNODE) return;
    int t = i / NNODE;
    int n = i - t * NNODE;
    uint2 v;
    v.x = __float_as_uint(thresholds[i]);
    v.y = (unsigned)features[i] * (SCHUNK * 4);   // pre-scaled shared-mem byte offset
    g_nodes[t * NPAD + n] = v;
}

// ---------------- prep: transpose x ----------------
__global__ void transpose_k(const float* __restrict__ x) {
    __shared__ float tile[32][33];
    int f0 = blockIdx.x * 32, s0 = blockIdx.y * 32;
    int lx = threadIdx.x, ly = threadIdx.y;  // blockDim (32,8)
    #pragma unroll
    for (int k = ly; k < 32; k += 8)
        tile[k][lx] = x[(size_t)(s0 + k) * NFEAT + f0 + lx];   // coalesced read
    __syncthreads();
    #pragma unroll
    for (int k = ly; k < 32; k += 8)
        g_xT[(size_t)(f0 + k) * BATCH + s0 + lx] = tile[lx][k]; // coalesced write
}

// ---------------- main traversal ----------------
__global__ __launch_bounds__(THREADS)
void traverse_k(const float* __restrict__ values, float* __restrict__ out) {
    extern __shared__ float xs[];   // [NFEAT][SCHUNK] = 128KB, conflict-free gather layout

    // Stage this block's 128 sample columns (coalesced from g_xT, conflict-free STS)
    int s0 = blockIdx.x * SCHUNK;
    for (int i = threadIdx.x; i < NFEAT * SCHUNK; i += THREADS)
        xs[i] = g_xT[(unsigned)(i >> 7) * BATCH + s0 + (i & (SCHUNK - 1))];
    __syncthreads();

    unsigned xaddr;
    asm("{ .reg .u64 t; cvta.to.shared.u64 t, %1; cvt.u32.u64 %0, t; }"
        : "=r"(xaddr) : "l"(xs));
    int sl = threadIdx.x & (SCHUNK - 1);
    int tl = threadIdx.x >> 7;            // 0..3 tree lanes
    xaddr += sl * 4;                      // thread's sample column base

    int s = s0 + sl;
    float* orow = out + (size_t)s * (NTREE * NCLS);
    const char* nb = (const char*)g_nodes;

    for (int tb = 0; tb < NTREE; tb += 8) {
        int tA = tb + tl * 2;
        int tB = tA + 1;
        unsigned baseA = (unsigned)tA * (NPAD * 8);
        unsigned baseB = (unsigned)tB * (NPAD * 8);
        unsigned offA = baseA, offB = baseB;            // global byte offsets into g_nodes
        unsigned cA8  = 8u  - baseA, cA16 = 16u - baseA; // fold tree base into the step constant
        unsigned cB8  = 8u  - baseB, cB16 = 16u - baseB;

        #pragma unroll
        for (int d = 0; d < DEPTH; d++) {
            uint2 a = __ldg((const uint2*)(nb + offA));
            uint2 b = __ldg((const uint2*)(nb + offB));
            float fa, fb;
            asm("ld.shared.f32 %0, [%1];" : "=f"(fa) : "r"(xaddr + a.y));
            asm("ld.shared.f32 %0, [%1];" : "=f"(fb) : "r"(xaddr + b.y));
            // off' = 2*off + 8(1+p) in-tree, with tree base folded via cX8/cX16
            offA = offA * 2u + ((fa >= __uint_as_float(a.x)) ? cA16 : cA8);
            offB = offB * 2u + ((fb >= __uint_as_float(b.x)) ? cB16 : cB8);
        }

        // leaf node index (global padded) -> values row index t*2047 + leaf
        unsigned vA = (offA >> 3) - (unsigned)tA;   // tA*2048 + leaf - tA = tA*2047 + leaf
        unsigned vB = (offB >> 3) - (unsigned)tB;
        const float4* pvA = (const float4*)values + (size_t)vA * 2;
        const float4* pvB = (const float4*)values + (size_t)vB * 2;
        float4 a0 = __ldg(pvA), a1 = __ldg(pvA + 1);
        float4 b0 = __ldg(pvB), b1 = __ldg(pvB + 1);
        float4* oA = (float4*)(orow + tA * NCLS);
        oA[0] = a0; oA[1] = a1;
        float4* oB = (float4*)(orow + tB * NCLS);
        oB[0] = b0; oB[1] = b1;
    }
}

extern "C" void kernel_launch(void* const* d_in, const int* in_sizes, int n_in,
                              void* d_out, int out_size) {
    // metadata order: x, lefts, rights, features, thresholds, values, nodes_offset
    const float* x          = (const float*)d_in[0];
    const int*   features   = (const int*)  d_in[3];
    const float* thresholds = (const float*)d_in[4];
    const float* values     = (const float*)d_in[5];

    cudaFuncSetAttribute(traverse_k, cudaFuncAttributeMaxDynamicSharedMemorySize,
                         NFEAT * SCHUNK * 4);

    prep_nodes_k<<<(NTREE * NNODE + 255) / 256, 256>>>(features, thresholds);
    transpose_k<<<dim3(NFEAT / 32, BATCH / 32), dim3(32, 8)>>>(x);
    traverse_k<<<BATCH / SCHUNK, THREADS, NFEAT * SCHUNK * 4>>>(values, (float*)d_out);
}

// round 2
// speedup vs baseline: 1.3166x; 1.3166x over previous
#include <cuda_runtime.h>
#include <stdint.h>

#define BATCH   32768
#define NTREE   256
#define NNODE   2047
#define NFEAT   256
#define NCLS    8
#define DEPTH   10
#define SCHUNK  128          // samples per block
#define THREADS 512          // 128 samples x 4 tree-lanes (2 chains each)
#define GTREES  8            // trees per shared-memory group
#define NGROUPS (NTREE / GTREES)
#define NSLOT   1024         // padded internal-node count per tree (1023 used)

// smem map (dynamic): [0,128KB) x-tile  [128KB,192KB) nodes / (idx 4KB + stage 34KB)
#define SM_X      0
#define SM_NODES  131072
#define SM_IDX    131072
#define SM_STAGE  (131072 + 4096)
#define SM_TOTAL  (131072 + 65536)
#define STG_PITCH 68         // floats per staged sample row (64 + 4 pad, kills bank conflicts)

__device__ uint2 g_nodes2[NTREE * NSLOT];   // internal nodes only: {thr bits, feat*512}
__device__ float g_xT[NFEAT * BATCH];       // x transposed [feature][sample]

// ---------------- prep: pack internal nodes ----------------
__global__ void prep_nodes_k(const int* __restrict__ features,
                             const float* __restrict__ thresholds) {
    int i = blockIdx.x * blockDim.x + threadIdx.x;
    if (i >= NTREE * 1023) return;
    int t = i / 1023;
    int n = i - t * 1023;                  // internal node id 0..1022
    int src = t * NNODE + n;
    uint2 v;
    v.x = __float_as_uint(thresholds[src]);
    v.y = (unsigned)features[src] * (SCHUNK * 4);   // smem byte offset of feature row
    g_nodes2[t * NSLOT + n] = v;
}

// ---------------- prep: transpose x ----------------
__global__ void transpose_k(const float* __restrict__ x) {
    __shared__ float tile[32][33];
    int f0 = blockIdx.x * 32, s0 = blockIdx.y * 32;
    int lx = threadIdx.x, ly = threadIdx.y;          // blockDim (32,8)
    #pragma unroll
    for (int k = ly; k < 32; k += 8)
        tile[k][lx] = x[(size_t)(s0 + k) * NFEAT + f0 + lx];
    __syncthreads();
    #pragma unroll
    for (int k = ly; k < 32; k += 8)
        g_xT[(size_t)(f0 + k) * BATCH + s0 + lx] = tile[lx][k];
}

// ---------------- main traversal ----------------
__global__ __launch_bounds__(THREADS)
void traverse_k(const float* __restrict__ values, float* __restrict__ out) {
    extern __shared__ char sm[];
    float* xs = (float*)(sm + SM_X);

    int tid = threadIdx.x;
    int s0 = blockIdx.x * SCHUNK;

    // Stage x tile [feat][sample], sample-minor (conflict-free gather layout)
    for (int i = tid; i < NFEAT * SCHUNK; i += THREADS)
        xs[i] = g_xT[(unsigned)(i >> 7) * BATCH + s0 + (i & (SCHUNK - 1))];

    unsigned smbase;
    asm("{ .reg .u64 t; cvta.to.shared.u64 t, %1; cvt.u32.u64 %0, t; }"
        : "=r"(smbase) : "l"(sm));
    int sl = tid & (SCHUNK - 1);
    int tl = tid >> 7;                    // 0..3
    unsigned xaddr = smbase + SM_X + sl * 4;

    int tA = 2 * tl, tB = 2 * tl + 1;     // trees-in-group for this thread's 2 chains
    unsigned baseA = smbase + SM_NODES + tA * (NSLOT * 8);
    unsigned baseB = smbase + SM_NODES + tB * (NSLOT * 8);
    unsigned cA = 8u - baseA, cB = 8u - baseB;   // fold base into step constant

    for (int g = 0; g < NGROUPS; g++) {
        int t0 = g * GTREES;
        __syncthreads();   // x ready (g==0) / prev copy-out complete

        // ---- stage group's node tables: 8 trees x 1024 x 8B = 4096 uint4, coalesced
        {
            const uint4* src = (const uint4*)(g_nodes2 + t0 * NSLOT);
            uint4* dst = (uint4*)(sm + SM_NODES);
            #pragma unroll
            for (int j = 0; j < 8; j++)
                dst[tid + THREADS * j] = __ldg(src + tid + THREADS * j);
        }
        __syncthreads();

        // ---- traversal: 2 interleaved chains, all loads from shared
        unsigned oA = baseA, oB = baseB;
        #pragma unroll
        for (int d = 0; d < DEPTH; d++) {
            unsigned ax, ay, bx, by;
            asm("ld.shared.v2.u32 {%0,%1}, [%2];" : "=r"(ax), "=r"(ay) : "r"(oA));
            asm("ld.shared.v2.u32 {%0,%1}, [%2];" : "=r"(bx), "=r"(by) : "r"(oB));
            float fa, fb;
            asm("ld.shared.f32 %0, [%1];" : "=f"(fa) : "r"(xaddr + ay));
            asm("ld.shared.f32 %0, [%1];" : "=f"(fb) : "r"(xaddr + by));
            oA = oA * 2u + cA + ((fa >= __uint_as_float(ax)) ? 8u : 0u);
            oB = oB * 2u + cB + ((fb >= __uint_as_float(bx)) ? 8u : 0u);
        }
        unsigned leafA = (oA - baseA) >> 3;   // 1023..2046
        unsigned leafB = (oB - baseB) >> 3;
        __syncthreads();   // done reading nodes smem -> safe to reuse

        // ---- publish values-row indices (conflict-free STS)
        unsigned* idxb = (unsigned*)(sm + SM_IDX);
        idxb[tA * SCHUNK + sl] = (unsigned)(t0 + tA) * NNODE + leafA;
        idxb[tB * SCHUNK + sl] = (unsigned)(t0 + tB) * NNODE + leafB;
        __syncthreads();

        // ---- cooperative values gather: 2048 half-row tasks, 2 lanes per 32B row
        float* stage = (float*)(sm + SM_STAGE);
        #pragma unroll
        for (int j = 0; j < 4; j++) {
            int task = tid + THREADS * j;
            int row  = task >> 1;            // (treeInGroup, sample)
            int half = task & 1;
            unsigned vrow = idxb[row];
            float4 v = __ldg((const float4*)values + (size_t)vrow * 2 + half);
            int rg = row >> 7, rs = row & (SCHUNK - 1);
            *(float4*)(stage + rs * STG_PITCH + rg * NCLS + half * 4) = v;
        }
        __syncthreads();

        // ---- coalesced copy-out: 64 contiguous floats per sample
        float* obase = out + (size_t)s0 * (NTREE * NCLS) + t0 * NCLS;
        #pragma unroll
        for (int j = 0; j < 4; j++) {
            int e  = tid + THREADS * j;
            int os = e >> 4, oc = e & 15;
            float4 v = *(const float4*)(stage + os * STG_PITCH + oc * 4);
            *(float4*)(obase + (size_t)os * (NTREE * NCLS) + oc * 4) = v;
        }
    }
}

extern "C" void kernel_launch(void* const* d_in, const int* in_sizes, int n_in,
                              void* d_out, int out_size) {
    // metadata order: x, lefts, rights, features, thresholds, values, nodes_offset
    const float* x          = (const float*)d_in[0];
    const int*   features   = (const int*)  d_in[3];
    const float* thresholds = (const float*)d_in[4];
    const float* values     = (const float*)d_in[5];

    cudaFuncSetAttribute(traverse_k, cudaFuncAttributeMaxDynamicSharedMemorySize, SM_TOTAL);

    prep_nodes_k<<<(NTREE * 1023 + 255) / 256, 256>>>(features, thresholds);
    transpose_k<<<dim3(NFEAT / 32, BATCH / 32), dim3(32, 8)>>>(x);
    traverse_k<<<BATCH / SCHUNK, THREADS, SM_TOTAL>>>(values, (float*)d_out);
}

// round 3
// speedup vs baseline: 2.3796x; 1.8074x over previous
#include <cuda_runtime.h>
#include <stdint.h>

#define BATCH   32768
#define NTREE   256
#define NNODE   2047
#define NFEAT   256
#define NCLS    8
#define DEPTH   10
#define SCHUNK  128
#define THREADS 512           // 128 samples x 4 tree-lanes (2 chains each)
#define GTREES  8
#define NGROUPS (NTREE / GTREES)
#define NSLOT   1024          // 8KB slab per tree (1023 internal nodes used)

// smem map: [0,128K) x-tile | [128K,192K) node buffer | [192K, +4.5K) idx
#define SM_X      0
#define SM_NODES  131072
#define SM_IDX    196608
#define IDX_PITCH 9           // words per sample row (8 trees + 1 pad)
#define SM_TOTAL  (196608 + SCHUNK * IDX_PITCH * 4)

__device__ uint2 g_nodes2[NTREE * NSLOT];   // internal nodes: {thr bits, feat*512}
__device__ float g_xT[NFEAT * BATCH];       // x transposed [feature][sample]

// ---------------- merged prep: transpose x + pack nodes ----------------
__global__ void prep_k(const float* __restrict__ x,
                       const int* __restrict__ features,
                       const float* __restrict__ thresholds) {
    int b = blockIdx.x;
    if (b < (NFEAT / 32) * (BATCH / 32)) {
        __shared__ float tile[32][33];
        int f0 = (b & 7) * 32, s0 = (b >> 3) * 32;
        int lx = threadIdx.x & 31, ly = threadIdx.x >> 5;   // 256 threads
        #pragma unroll
        for (int k = ly; k < 32; k += 8)
            tile[k][lx] = x[(size_t)(s0 + k) * NFEAT + f0 + lx];
        __syncthreads();
        #pragma unroll
        for (int k = ly; k < 32; k += 8)
            g_xT[(size_t)(f0 + k) * BATCH + s0 + lx] = tile[lx][k];
    } else {
        int i = (b - (NFEAT / 32) * (BATCH / 32)) * 256 + threadIdx.x;
        if (i < NTREE * 1023) {
            int t = i / 1023;
            int n = i - t * 1023;
            int src = t * NNODE + n;
            uint2 v;
            v.x = __float_as_uint(thresholds[src]);
            v.y = (unsigned)features[src] * (SCHUNK * 4);
            g_nodes2[t * NSLOT + n] = v;
        }
    }
}

// ---------------- main traversal ----------------
__device__ __forceinline__ void prefetch_group(unsigned dstbase, int g, int tid) {
    // 8 trees x 1024 x 8B = 64KB via cp.async, 128B per thread, coalesced
    const char* src = (const char*)(g_nodes2 + g * GTREES * NSLOT);
    #pragma unroll
    for (int k = 0; k < 8; k++) {
        unsigned dst = dstbase + (unsigned)(k * THREADS + tid) * 16;
        const char* s = src + (size_t)(k * THREADS + tid) * 16;
        asm volatile("cp.async.cg.shared.global [%0], [%1], 16;"
                     :: "r"(dst), "l"(s) : "memory");
    }
    asm volatile("cp.async.commit_group;" ::: "memory");
}

__global__ __launch_bounds__(THREADS, 1)
void traverse_k(const float* __restrict__ values, float* __restrict__ out) {
    extern __shared__ char sm[];
    float* xs = (float*)(sm + SM_X);
    unsigned* idxb = (unsigned*)(sm + SM_IDX);

    int tid = threadIdx.x;
    int s0 = blockIdx.x * SCHUNK;

    unsigned smbase;
    asm("{ .reg .u64 t; cvta.to.shared.u64 t, %1; cvt.u32.u64 %0, t; }"
        : "=r"(smbase) : "l"(sm));

    // kick off node prefetch for group 0 first (longest latency)
    prefetch_group(smbase + SM_NODES, 0, tid);

    // stage x tile [feat][sample], sample-minor (conflict-free gather layout)
    for (int i = tid; i < NFEAT * SCHUNK; i += THREADS)
        xs[i] = g_xT[(unsigned)(i >> 7) * BATCH + s0 + (i & (SCHUNK - 1))];

    int sl = tid & (SCHUNK - 1);
    int tl = tid >> 7;                       // 0..3
    unsigned xaddr = smbase + SM_X + sl * 4;

    int tA = 2 * tl, tB = 2 * tl + 1;        // trees-in-group for this thread
    unsigned baseA = smbase + SM_NODES + tA * (NSLOT * 8);
    unsigned baseB = smbase + SM_NODES + tB * (NSLOT * 8);
    unsigned cA = 8u - baseA, cB = 8u - baseB;

    for (int g = 0; g < NGROUPS; g++) {
        int t0 = g * GTREES;
        asm volatile("cp.async.wait_group 0;" ::: "memory");
        __syncthreads();                     // nodes[g] ready (and x ready for g=0)

        // ---- traversal: 2 interleaved chains, all loads from shared
        unsigned oA = baseA, oB = baseB;
        #pragma unroll
        for (int d = 0; d < DEPTH; d++) {
            unsigned ax, ay, bx, by;
            asm("ld.shared.v2.u32 {%0,%1}, [%2];" : "=r"(ax), "=r"(ay) : "r"(oA));
            asm("ld.shared.v2.u32 {%0,%1}, [%2];" : "=r"(bx), "=r"(by) : "r"(oB));
            float fa, fb;
            asm("ld.shared.f32 %0, [%1];" : "=f"(fa) : "r"(xaddr + ay));
            asm("ld.shared.f32 %0, [%1];" : "=f"(fb) : "r"(xaddr + by));
            oA = oA * 2u + cA + ((fa >= __uint_as_float(ax)) ? 8u : 0u);
            oB = oB * 2u + cB + ((fb >= __uint_as_float(bx)) ? 8u : 0u);
        }
        unsigned leafA = (oA - baseA) >> 3;  // 1023..2046
        unsigned leafB = (oB - baseB) >> 3;
        __syncthreads();                     // done reading nodes smem

        // prefetch next group's nodes while we gather/store (overlapped)
        prefetch_group(smbase + SM_NODES, (g + 1 < NGROUPS) ? g + 1 : 0, tid);

        // ---- publish values-row indices (conflict-free: pitch 9)
        idxb[sl * IDX_PITCH + tA] = (unsigned)(t0 + tA) * NNODE + leafA;
        idxb[sl * IDX_PITCH + tB] = (unsigned)(t0 + tB) * NNODE + leafB;
        __syncthreads();                     // idx ready

        // ---- gather values, write DIRECTLY to gmem, coalesced by output order
        // task e: sl2 = e>>4, r = e&15, tg = r>>1, half = r&1
        float* obase = out + (size_t)s0 * (NTREE * NCLS) + t0 * NCLS;
        #pragma unroll
        for (int j = 0; j < 4; j++) {
            int e   = tid + THREADS * j;
            int sl2 = e >> 4;
            int tg  = (e >> 1) & 7;
            int half = e & 1;
            unsigned vrow = idxb[sl2 * IDX_PITCH + tg];
            float4 v = __ldg((const float4*)values + (size_t)vrow * 2 + half);
            *(float4*)(obase + (size_t)sl2 * (NTREE * NCLS) + tg * NCLS + half * 4) = v;
        }
        // loop-top barrier (after wait_group) protects idxb reuse next group
    }
}

extern "C" void kernel_launch(void* const* d_in, const int* in_sizes, int n_in,
                              void* d_out, int out_size) {
    // metadata order: x, lefts, rights, features, thresholds, values, nodes_offset
    const float* x          = (const float*)d_in[0];
    const int*   features   = (const int*)  d_in[3];
    const float* thresholds = (const float*)d_in[4];
    const float* values     = (const float*)d_in[5];

    cudaFuncSetAttribute(traverse_k, cudaFuncAttributeMaxDynamicSharedMemorySize, SM_TOTAL);

    int prep_blocks = (NFEAT / 32) * (BATCH / 32) + (NTREE * 1023 + 255) / 256;
    prep_k<<<prep_blocks, 256>>>(x, features, thresholds);
    traverse_k<<<BATCH / SCHUNK, THREADS, SM_TOTAL>>>(values, (float*)d_out);
}